// round 11
// baseline (speedup 1.0000x reference)
#include <cuda_runtime.h>
#include <cuda_fp16.h>
#include <cstdint>

#define B_      16
#define S_      2048
#define D_      512
#define BR      64
#define BC      64
#define PITCH   520   // halves per row, Q/V smem tiles (512 + 8 pad)
#define KCH     256   // K chunk width (cols of D)
#define KPITCH  264   // halves per row, K chunk buffer (256 + 8 pad)
#define NCHUNK  2     // 512 / 256
#define PPITCH  72    // halves per row for P tile
#define NTHREAD 512

// fp16 scratch (one-time converted copies of Q, K, V)
__device__ half Qh[B_ * S_ * D_];
__device__ half Kh[B_ * S_ * D_];
__device__ half Vh[B_ * S_ * D_];

__device__ __forceinline__ uint32_t smem_u32(const void* p) {
    return (uint32_t)__cvta_generic_to_shared(p);
}
__device__ __forceinline__ void cp16(uint32_t saddr, const void* gptr) {
    asm volatile("cp.async.cg.shared.global [%0], [%1], 16;\n" :: "r"(saddr), "l"(gptr));
}
#define CP_COMMIT() asm volatile("cp.async.commit_group;\n" ::: "memory")
#define CP_WAIT0()  asm volatile("cp.async.wait_group 0;\n" ::: "memory")
#define CP_WAIT1()  asm volatile("cp.async.wait_group 1;\n" ::: "memory")

__device__ __forceinline__ void ldmatrix_x4(uint32_t& r0, uint32_t& r1, uint32_t& r2, uint32_t& r3, uint32_t addr) {
    asm volatile("ldmatrix.sync.aligned.m8n8.x4.shared.b16 {%0,%1,%2,%3}, [%4];"
                 : "=r"(r0), "=r"(r1), "=r"(r2), "=r"(r3) : "r"(addr));
}
__device__ __forceinline__ void ldmatrix_x4_trans(uint32_t& r0, uint32_t& r1, uint32_t& r2, uint32_t& r3, uint32_t addr) {
    asm volatile("ldmatrix.sync.aligned.m8n8.x4.trans.shared.b16 {%0,%1,%2,%3}, [%4];"
                 : "=r"(r0), "=r"(r1), "=r"(r2), "=r"(r3) : "r"(addr));
}
__device__ __forceinline__ void mma16816(float* c, uint32_t a0, uint32_t a1, uint32_t a2, uint32_t a3,
                                         uint32_t b0, uint32_t b1) {
    asm volatile("mma.sync.aligned.m16n8k16.row.col.f32.f16.f16.f32 "
                 "{%0,%1,%2,%3}, {%4,%5,%6,%7}, {%8,%9}, {%0,%1,%2,%3};"
                 : "+f"(c[0]), "+f"(c[1]), "+f"(c[2]), "+f"(c[3])
                 : "r"(a0), "r"(a1), "r"(a2), "r"(a3), "r"(b0), "r"(b1));
}

// ---- fp32 -> fp16 conversion pre-pass (which: 0=Q, 1=K, 2=V) ----
// Q is pre-scaled by log2(e)/sqrt(512) so S accumulates in the exp2 domain.
__global__ __launch_bounds__(256)
void cvt_kernel(const float* __restrict__ src, int which) {
    half* dst = (which == 0) ? Qh : (which == 1) ? Kh : Vh;
    const float sc = (which == 0) ? 0.06376207819900912f : 1.0f;  // log2e/sqrt(512)
    size_t base = ((size_t)blockIdx.x * 256 + threadIdx.x) * 4;
    float4 v = *(const float4*)(src + base);
    half2 h0 = __floats2half2_rn(v.x * sc, v.y * sc);
    half2 h1 = __floats2half2_rn(v.z * sc, v.w * sc);
    uint2 pk; pk.x = *(uint32_t*)&h0; pk.y = *(uint32_t*)&h1;
    *(uint2*)(dst + base) = pk;
}

__global__ __launch_bounds__(NTHREAD, 1)
void attn_fa_kernel(float* __restrict__ Og)
{
    extern __shared__ char smem[];
    half*  Qs   = (half*)smem;                        // [BR][PITCH]
    half*  Ks   = Qs + BR * PITCH;                    // 2 x [BC][KPITCH]
    half*  Vs   = Ks + 2 * BC * KPITCH;               // [BC][PITCH]
    half*  Ps   = Vs + BC * PITCH;                    // [BR][PPITCH]
    float* sMax = (float*)(Ps + BR * PPITCH);         // [BR][4]
    float* sSum = sMax + BR * 4;                      // [BR][4]
    float* sA   = sSum + BR * 4;                      // [BR]
    float* sL   = sA + BR;                            // [BR]

    const int tid  = threadIdx.x;
    const int lane = tid & 31;
    const int w    = tid >> 5;     // 0..15
    const int rg   = w >> 2;       // S row group (0..3): rows 16*rg
    const int cg   = w & 3;        // S col group (0..3): cols 16*cg
    const int qt   = (int)gridDim.x - 1 - blockIdx.x;  // reversed: big tiles first
    const int b    = blockIdx.y;

    if (tid < BR) sL[tid] = 0.0f;

    const half* qg = Qh + (size_t)(b * S_ + qt * BR) * D_;

    // ---- prologue: async-load Q tile, then K chunk 0 of j=0 ----
    for (int s = tid; s < BR * 64; s += NTHREAD) {          // 4096 segs of 16B
        int r = s >> 6, cs = s & 63;
        cp16(smem_u32(&Qs[r * PITCH + cs * 8]), qg + (size_t)r * D_ + cs * 8);
    }
    CP_COMMIT();
    {
        const half* kg0 = Kh + (size_t)(b * S_) * D_;       // j = 0, chunk 0
        for (int s = tid; s < 2048; s += NTHREAD) {         // 64 rows x 32 segs
            int r = s >> 5, cs = s & 31;
            cp16(smem_u32(&Ks[r * KPITCH + cs * 8]), kg0 + (size_t)r * D_ + cs * 8);
        }
    }
    CP_COMMIT();

    // accO: 64 rows x 32 D-cols per warp
    float accO[4][4][4];
    #pragma unroll
    for (int mt = 0; mt < 4; mt++)
        #pragma unroll
        for (int nt = 0; nt < 4; nt++)
            #pragma unroll
            for (int i = 0; i < 4; i++) accO[mt][nt][i] = 0.0f;

    // per-thread running row max (log2 domain) for the 2 S-rows this thread owns
    float mrow0 = -1e30f, mrow1 = -1e30f;

    const int r0 = 16 * rg + (lane >> 2);
    const int r1 = r0 + 8;

    for (int j = 0; j <= qt; j++) {
        const half* kg = Kh + (size_t)(b * S_ + j * BC) * D_;
        const half* vg = Vh + (size_t)(b * S_ + j * BC) * D_;

        float accS[2][4];
        #pragma unroll
        for (int nt = 0; nt < 2; nt++)
            #pragma unroll
            for (int i = 0; i < 4; i++) accS[nt][i] = 0.0f;

        // ---- S = Q K^T (log2 domain), 2 chunks of 256, K double-buffered ----
        #pragma unroll
        for (int c = 0; c < NCHUNK; c++) {
            if (c == 0) { CP_WAIT0(); } else { CP_WAIT1(); }   // K chunk c resident; V may float
            __syncthreads();

            if (c == 0) {
                // K chunk 1 (own group, committed FIRST so wait_group 1 drains it)
                half* kb1 = Ks + BC * KPITCH;
                const half* kgc = kg + KCH;
                for (int s = tid; s < 2048; s += NTHREAD) {
                    int r = s >> 5, cs = s & 31;
                    cp16(smem_u32(&kb1[r * KPITCH + cs * 8]), kgc + (size_t)r * D_ + cs * 8);
                }
                CP_COMMIT();
                // V half 0 (rows 0..31), separate group
                for (int s = tid; s < 2048; s += NTHREAD) {
                    int r = s >> 6, cs = s & 63;
                    cp16(smem_u32(&Vs[r * PITCH + cs * 8]), vg + (size_t)r * D_ + cs * 8);
                }
                CP_COMMIT();
            } else {
                // V half 1 (rows 32..63)
                for (int s = tid; s < 2048; s += NTHREAD) {
                    int r = 32 + (s >> 6), cs = s & 63;
                    cp16(smem_u32(&Vs[r * PITCH + cs * 8]), vg + (size_t)r * D_ + cs * 8);
                }
                CP_COMMIT();
                if (j < qt) {    // prefetch K chunk 0 of next j into buffer 0
                    const half* kgn = kg + (size_t)BC * D_;
                    for (int s = tid; s < 2048; s += NTHREAD) {
                        int r = s >> 5, cs = s & 31;
                        cp16(smem_u32(&Ks[r * KPITCH + cs * 8]), kgn + (size_t)r * D_ + cs * 8);
                    }
                    CP_COMMIT();
                }
            }

            // MMA over chunk c (16 k-steps of 16) — fully unrolled for LDSM MLP
            const half* kb = Ks + c * BC * KPITCH;
            #pragma unroll
            for (int kk = 0; kk < 16; kk++) {
                // K fragment for both nt via one x4:
                // lanes 0-7: nt0.b0, 8-15: nt1.b0, 16-23: nt0.b1, 24-31: nt1.b1
                int br = 16 * cg + ((lane >> 3) & 1) * 8 + (lane & 7);
                int bc = kk * 16 + (lane >> 4) * 8;
                uint32_t b0, b1, b2, b3;
                ldmatrix_x4(b0, b1, b2, b3, smem_u32(&kb[br * KPITCH + bc]));

                int ar = 16 * rg + (lane & 7) + ((lane >> 3) & 1) * 8;
                int ac = c * KCH + kk * 16 + (lane >> 4) * 8;
                uint32_t a0, a1, a2, a3;
                ldmatrix_x4(a0, a1, a2, a3, smem_u32(&Qs[ar * PITCH + ac]));

                mma16816(accS[0], a0, a1, a2, a3, b0, b2);
                mma16816(accS[1], a0, a1, a2, a3, b1, b3);
            }
        }

        // ---- causal mask in regs (log2 domain; no scale needed) ----
        const bool diag = (j == qt);
        if (diag) {
            #pragma unroll
            for (int nt = 0; nt < 2; nt++) {
                int cl = 16 * cg + 8 * nt + (lane & 3) * 2;
                if (cl     > r0) accS[nt][0] = -1e30f;
                if (cl + 1 > r0) accS[nt][1] = -1e30f;
                if (cl     > r1) accS[nt][2] = -1e30f;
                if (cl + 1 > r1) accS[nt][3] = -1e30f;
            }
        }

        // ---- one-pass softmax: local (max, expsum) pairs -> single combine ----
        float mx0 = fmaxf(fmaxf(accS[0][0], accS[0][1]), fmaxf(accS[1][0], accS[1][1]));
        float mx1 = fmaxf(fmaxf(accS[0][2], accS[0][3]), fmaxf(accS[1][2], accS[1][3]));
        mx0 = fmaxf(mx0, __shfl_xor_sync(0xffffffffu, mx0, 1));
        mx0 = fmaxf(mx0, __shfl_xor_sync(0xffffffffu, mx0, 2));
        mx1 = fmaxf(mx1, __shfl_xor_sync(0xffffffffu, mx1, 1));
        mx1 = fmaxf(mx1, __shfl_xor_sync(0xffffffffu, mx1, 2));

        float p[2][4];
        #pragma unroll
        for (int nt = 0; nt < 2; nt++) {
            p[nt][0] = exp2f(accS[nt][0] - mx0);
            p[nt][1] = exp2f(accS[nt][1] - mx0);
            p[nt][2] = exp2f(accS[nt][2] - mx1);
            p[nt][3] = exp2f(accS[nt][3] - mx1);
        }
        float s0 = p[0][0] + p[0][1] + p[1][0] + p[1][1];
        float s1 = p[0][2] + p[0][3] + p[1][2] + p[1][3];
        s0 += __shfl_xor_sync(0xffffffffu, s0, 1);
        s0 += __shfl_xor_sync(0xffffffffu, s0, 2);
        s1 += __shfl_xor_sync(0xffffffffu, s1, 1);
        s1 += __shfl_xor_sync(0xffffffffu, s1, 2);

        if ((lane & 3) == 0) {
            sMax[r0 * 4 + cg] = mx0;  sSum[r0 * 4 + cg] = s0;
            sMax[r1 * 4 + cg] = mx1;  sSum[r1 * 4 + cg] = s1;
        }
        __syncthreads();   // barrier A: (max, sum) pairs visible

        float4 pm0 = *(float4*)&sMax[r0 * 4];
        float4 pm1 = *(float4*)&sMax[r1 * 4];
        float mnew0 = fmaxf(fmaxf(fmaxf(pm0.x, pm0.y), fmaxf(pm0.z, pm0.w)), mrow0);
        float mnew1 = fmaxf(fmaxf(fmaxf(pm1.x, pm1.y), fmaxf(pm1.z, pm1.w)), mrow1);

        // rescale this quad's p by exp2(local_max - global_max)
        float f0 = exp2f(mx0 - mnew0);
        float f1 = exp2f(mx1 - mnew1);
        float alpha0 = exp2f(mrow0 - mnew0);
        float alpha1 = exp2f(mrow1 - mnew1);
        mrow0 = mnew0; mrow1 = mnew1;

        // stage P (fp16) for the PV mma
        #pragma unroll
        for (int nt = 0; nt < 2; nt++) {
            int cl = 16 * cg + 8 * nt + (lane & 3) * 2;
            *(half2*)&Ps[r0 * PPITCH + cl] = __floats2half2_rn(p[nt][0] * f0, p[nt][1] * f0);
            *(half2*)&Ps[r1 * PPITCH + cl] = __floats2half2_rn(p[nt][2] * f1, p[nt][3] * f1);
        }

        // row owner (cg==0 quad leader) publishes alpha and updates sL
        if (cg == 0 && (lane & 3) == 0) {
            sA[r0] = alpha0;
            sA[r1] = alpha1;
            float4 ps0 = *(float4*)&sSum[r0 * 4];
            float4 ps1 = *(float4*)&sSum[r1 * 4];
            float g0 = ps0.x * exp2f(pm0.x - mnew0) + ps0.y * exp2f(pm0.y - mnew0)
                     + ps0.z * exp2f(pm0.z - mnew0) + ps0.w * exp2f(pm0.w - mnew0);
            float g1 = ps1.x * exp2f(pm1.x - mnew1) + ps1.y * exp2f(pm1.y - mnew1)
                     + ps1.z * exp2f(pm1.z - mnew1) + ps1.w * exp2f(pm1.w - mnew1);
            sL[r0] = sL[r0] * alpha0 + g0;
            sL[r1] = sL[r1] * alpha1 + g1;
        }

        // V halves must be resident (next-j K0 prefetch may stay in flight)
        if (j < qt) { CP_WAIT1(); } else { CP_WAIT0(); }
        __syncthreads();   // barrier B: P, alphas, sL, V visible

        // ---- rescale O, then O += P V : warp w owns cols [32w, 32w+32) ----
        #pragma unroll
        for (int mt = 0; mt < 4; mt++) {
            float a0s = sA[mt * 16 + (lane >> 2)];
            float a1s = sA[mt * 16 + 8 + (lane >> 2)];
            #pragma unroll
            for (int nt = 0; nt < 4; nt++) {
                accO[mt][nt][0] *= a0s; accO[mt][nt][1] *= a0s;
                accO[mt][nt][2] *= a1s; accO[mt][nt][3] *= a1s;
            }
        }
        #pragma unroll
        for (int kk = 0; kk < 4; kk++) {
            const int k0 = kk * 16;
            uint32_t bb[4][2];
            #pragma unroll
            for (int h = 0; h < 2; h++) {
                // V fragments for nt pair {2h, 2h+1} via one x4.trans
                int vr = k0 + ((lane >> 3) & 1) * 8 + (lane & 7);
                int vc = w * 32 + h * 16 + (lane >> 4) * 8;
                uint32_t t0, t1, t2, t3;
                ldmatrix_x4_trans(t0, t1, t2, t3, smem_u32(&Vs[vr * PITCH + vc]));
                bb[2 * h][0] = t0; bb[2 * h][1] = t1;
                bb[2 * h + 1][0] = t2; bb[2 * h + 1][1] = t3;
            }
            #pragma unroll
            for (int mt = 0; mt < 4; mt++) {
                uint32_t a0, a1, a2, a3;
                int r = mt * 16 + (lane & 7) + ((lane >> 3) & 1) * 8;
                int c = k0 + (lane >> 4) * 8;
                ldmatrix_x4(a0, a1, a2, a3, smem_u32(&Ps[r * PPITCH + c]));
                #pragma unroll
                for (int nt = 0; nt < 4; nt++)
                    mma16816(accO[mt][nt], a0, a1, a2, a3, bb[nt][0], bb[nt][1]);
            }
        }
        // next iteration's chunk-0 barrier covers remaining hazards
    }

    __syncthreads();   // sL updates visible to all for the epilogue

    // ---- epilogue: O / l -> global ----
    float* obase = Og + (size_t)(b * S_ + qt * BR) * D_;
    #pragma unroll
    for (int mt = 0; mt < 4; mt++) {
        int er0 = mt * 16 + (lane >> 2);
        float il0 = 1.0f / sL[er0];
        float il1 = 1.0f / sL[er0 + 8];
        #pragma unroll
        for (int nt = 0; nt < 4; nt++) {
            int c = w * 32 + nt * 8 + (lane & 3) * 2;
            *(float2*)(obase + (size_t)er0 * D_ + c) =
                make_float2(accO[mt][nt][0] * il0, accO[mt][nt][1] * il0);
            *(float2*)(obase + (size_t)(er0 + 8) * D_ + c) =
                make_float2(accO[mt][nt][2] * il1, accO[mt][nt][3] * il1);
        }
    }
}

extern "C" void kernel_launch(void* const* d_in, const int* in_sizes, int n_in,
                              void* d_out, int out_size) {
    const float* Q = (const float*)d_in[0];
    const float* K = (const float*)d_in[1];
    const float* V = (const float*)d_in[2];
    float* O = (float*)d_out;

    // fp32 -> fp16 pre-pass (one-time per launch; Q pre-scaled to log2 domain)
    const int nblk = (B_ * S_ * D_) / (256 * 4);   // 16384
    cvt_kernel<<<nblk, 256>>>(Q, 0);
    cvt_kernel<<<nblk, 256>>>(K, 1);
    cvt_kernel<<<nblk, 256>>>(V, 2);

    const int smem_bytes = (BR * PITCH) * 2            // Q      66560
                         + (2 * BC * KPITCH) * 2       // K x2   67584
                         + (BC * PITCH) * 2            // V      66560
                         + BR * PPITCH * 2             // P       9216
                         + BR * 4 * 4                  // sMax    1024
                         + BR * 4 * 4                  // sSum    1024
                         + BR * 4                      // sA       256
                         + BR * 4;                     // sL       256
    cudaFuncSetAttribute(attn_fa_kernel, cudaFuncAttributeMaxDynamicSharedMemorySize, smem_bytes);

    dim3 grid(S_ / BR, B_);
    attn_fa_kernel<<<grid, NTHREAD, smem_bytes>>>(O);
}

// round 13
// speedup vs baseline: 1.0226x; 1.0226x over previous
#include <cuda_runtime.h>
#include <cuda_fp16.h>
#include <cstdint>

#define B_      16
#define S_      2048
#define D_      512
#define BR      64
#define BC      64
#define PITCH   520   // halves per row, Q/V smem tiles (512 + 8 pad)
#define KCH     256   // K chunk width (cols of D)
#define KPITCH  264   // halves per row, K chunk slot (256 + 8 pad)
#define PPITCH  72    // halves per row for P tile
#define NTHREAD 512

// fp16 scratch (one-time converted copies of Q, K, V)
__device__ half Qh[B_ * S_ * D_];
__device__ half Kh[B_ * S_ * D_];
__device__ half Vh[B_ * S_ * D_];

__device__ __forceinline__ uint32_t smem_u32(const void* p) {
    return (uint32_t)__cvta_generic_to_shared(p);
}
__device__ __forceinline__ void cp16(uint32_t saddr, const void* gptr) {
    asm volatile("cp.async.cg.shared.global [%0], [%1], 16;\n" :: "r"(saddr), "l"(gptr));
}
#define CP_COMMIT() asm volatile("cp.async.commit_group;\n" ::: "memory")
#define CP_WAIT0()  asm volatile("cp.async.wait_group 0;\n" ::: "memory")
#define CP_WAIT1()  asm volatile("cp.async.wait_group 1;\n" ::: "memory")

__device__ __forceinline__ void ldmatrix_x4(uint32_t& r0, uint32_t& r1, uint32_t& r2, uint32_t& r3, uint32_t addr) {
    asm volatile("ldmatrix.sync.aligned.m8n8.x4.shared.b16 {%0,%1,%2,%3}, [%4];"
                 : "=r"(r0), "=r"(r1), "=r"(r2), "=r"(r3) : "r"(addr));
}
__device__ __forceinline__ void ldmatrix_x4_trans(uint32_t& r0, uint32_t& r1, uint32_t& r2, uint32_t& r3, uint32_t addr) {
    asm volatile("ldmatrix.sync.aligned.m8n8.x4.trans.shared.b16 {%0,%1,%2,%3}, [%4];"
                 : "=r"(r0), "=r"(r1), "=r"(r2), "=r"(r3) : "r"(addr));
}
__device__ __forceinline__ void mma16816(float* c, uint32_t a0, uint32_t a1, uint32_t a2, uint32_t a3,
                                         uint32_t b0, uint32_t b1) {
    asm volatile("mma.sync.aligned.m16n8k16.row.col.f32.f16.f16.f32 "
                 "{%0,%1,%2,%3}, {%4,%5,%6,%7}, {%8,%9}, {%0,%1,%2,%3};"
                 : "+f"(c[0]), "+f"(c[1]), "+f"(c[2]), "+f"(c[3])
                 : "r"(a0), "r"(a1), "r"(a2), "r"(a3), "r"(b0), "r"(b1));
}

// ---- fp32 -> fp16 conversion pre-pass (which: 0=Q, 1=K, 2=V) ----
__global__ __launch_bounds__(256)
void cvt_kernel(const float* __restrict__ src, int which) {
    half* dst = (which == 0) ? Qh : (which == 1) ? Kh : Vh;
    size_t base = ((size_t)blockIdx.x * 256 + threadIdx.x) * 4;
    float4 v = *(const float4*)(src + base);
    half2 h0 = __floats2half2_rn(v.x, v.y);
    half2 h1 = __floats2half2_rn(v.z, v.w);
    uint2 pk; pk.x = *(uint32_t*)&h0; pk.y = *(uint32_t*)&h1;
    *(uint2*)(dst + base) = pk;
}

__global__ __launch_bounds__(NTHREAD, 1)
void attn_fa_kernel(float* __restrict__ Og)
{
    extern __shared__ char smem[];
    half*  Qs   = (half*)smem;                        // [BR][PITCH]
    half*  Kc   = Qs + BR * PITCH;                    // 2 slots x [BC][KPITCH]
    half*  VAb  = Kc + 2 * BC * KPITCH;               // [32][PITCH]
    half*  VBb  = VAb + 32 * PITCH;                   // [32][PITCH]
    half*  Ps   = VBb + 32 * PITCH;                   // [BR][PPITCH]
    float* sMax = (float*)(Ps + BR * PPITCH);         // [BR][4]
    float* sSum = sMax + BR * 4;                      // [BR][4]
    float* sA   = sSum + BR * 4;                      // [BR]
    float* sL   = sA + BR;                            // [BR]

    const int tid  = threadIdx.x;
    const int lane = tid & 31;
    const int w    = tid >> 5;     // 0..15
    const int rg   = w >> 2;       // S row group (0..3)
    const int cg   = w & 3;        // S col group (0..3)
    const int qt   = (int)gridDim.x - 1 - blockIdx.x;
    const int b    = blockIdx.y;

    if (tid < BR) sL[tid] = 0.0f;

    const half* qg = Qh + (size_t)(b * S_ + qt * BR) * D_;
    const half* kbase = Kh + (size_t)(b * S_) * D_;
    const half* vbase = Vh + (size_t)(b * S_) * D_;

    // ---- prologue: Q + K(0) both chunks ----
    for (int s = tid; s < 4096; s += NTHREAD) {           // Q: 64 rows x 64 segs
        int r = s >> 6, cs = s & 63;
        cp16(smem_u32(&Qs[r * PITCH + cs * 8]), qg + (size_t)r * D_ + cs * 8);
    }
    for (int c = 0; c < 2; c++) {
        half* slot = Kc + c * BC * KPITCH;
        const half* kgc = kbase + c * KCH;
        for (int s = tid; s < 2048; s += NTHREAD) {       // 64 rows x 32 segs
            int r = s >> 5, cs = s & 31;
            cp16(smem_u32(&slot[r * KPITCH + cs * 8]), kgc + (size_t)r * D_ + cs * 8);
        }
    }
    CP_COMMIT();
    CP_WAIT0();
    __syncthreads();

    float accS[2][4];
    #pragma unroll
    for (int nt = 0; nt < 2; nt++)
        #pragma unroll
        for (int i = 0; i < 4; i++) accS[nt][i] = 0.0f;

    // ---- S(0): straight 2 chunks x 16 kk ----
    for (int c = 0; c < 2; c++) {
        const half* kb = Kc + c * BC * KPITCH;
        #pragma unroll
        for (int kk = 0; kk < 16; kk++) {
            int br = 16 * cg + ((lane >> 3) & 1) * 8 + (lane & 7);
            int bc = kk * 16 + (lane >> 4) * 8;
            uint32_t b0, b1, b2, b3;
            ldmatrix_x4(b0, b1, b2, b3, smem_u32(&kb[br * KPITCH + bc]));
            int ar = 16 * rg + (lane & 7) + ((lane >> 3) & 1) * 8;
            int ac = c * KCH + kk * 16 + (lane >> 4) * 8;
            uint32_t a0, a1, a2, a3;
            ldmatrix_x4(a0, a1, a2, a3, smem_u32(&Qs[ar * PITCH + ac]));
            mma16816(accS[0], a0, a1, a2, a3, b0, b2);
            mma16816(accS[1], a0, a1, a2, a3, b1, b3);
        }
    }
    __syncthreads();   // all K(0)/Q reads done before any overwrite

    // ---- g2' = [VA(0), K(1)c0] ----
    for (int s = tid; s < 2048; s += NTHREAD) {
        int r = s >> 6, cs = s & 63;
        cp16(smem_u32(&VAb[r * PITCH + cs * 8]), vbase + (size_t)r * D_ + cs * 8);
    }
    if (qt >= 1) {
        const half* kg1 = kbase + (size_t)BC * D_;
        for (int s = tid; s < 2048; s += NTHREAD) {
            int r = s >> 5, cs = s & 31;
            cp16(smem_u32(&Kc[r * KPITCH + cs * 8]), kg1 + (size_t)r * D_ + cs * 8);
        }
    }
    CP_COMMIT();   // g2'

    float accO[4][4][4];
    #pragma unroll
    for (int mt = 0; mt < 4; mt++)
        #pragma unroll
        for (int nt = 0; nt < 4; nt++)
            #pragma unroll
            for (int i = 0; i < 4; i++) accO[mt][nt][i] = 0.0f;

    float mrow0 = -1e30f, mrow1 = -1e30f;
    const float inv_scale = 0.04419417382415922f;  // 1/sqrt(512)
    const int r0 = 16 * rg + (lane >> 2);
    const int r1 = r0 + 8;

    for (int j = 0; j <= qt; j++) {
        const bool more = (j < qt);

        // ---- softmax(j): scale + mask + local max ----
        #pragma unroll
        for (int nt = 0; nt < 2; nt++) {
            int cl = 16 * cg + 8 * nt + (lane & 3) * 2;
            accS[nt][0] *= inv_scale; accS[nt][1] *= inv_scale;
            accS[nt][2] *= inv_scale; accS[nt][3] *= inv_scale;
            if (j == qt) {
                if (cl     > r0) accS[nt][0] = -1e30f;
                if (cl + 1 > r0) accS[nt][1] = -1e30f;
                if (cl     > r1) accS[nt][2] = -1e30f;
                if (cl + 1 > r1) accS[nt][3] = -1e30f;
            }
        }
        float mx0 = fmaxf(fmaxf(accS[0][0], accS[0][1]), fmaxf(accS[1][0], accS[1][1]));
        float mx1 = fmaxf(fmaxf(accS[0][2], accS[0][3]), fmaxf(accS[1][2], accS[1][3]));
        mx0 = fmaxf(mx0, __shfl_xor_sync(0xffffffffu, mx0, 1));
        mx0 = fmaxf(mx0, __shfl_xor_sync(0xffffffffu, mx0, 2));
        mx1 = fmaxf(mx1, __shfl_xor_sync(0xffffffffu, mx1, 1));
        mx1 = fmaxf(mx1, __shfl_xor_sync(0xffffffffu, mx1, 2));
        if ((lane & 3) == 0) {
            sMax[r0 * 4 + cg] = mx0;
            sMax[r1 * 4 + cg] = mx1;
        }

        // ---- g1 = [K(j+1)c1, VB(j)] ----
        if (more) {
            const half* kg1 = kbase + (size_t)((j + 1) * BC) * D_ + KCH;
            half* slot1 = Kc + BC * KPITCH;
            for (int s = tid; s < 2048; s += NTHREAD) {
                int r = s >> 5, cs = s & 31;
                cp16(smem_u32(&slot1[r * KPITCH + cs * 8]), kg1 + (size_t)r * D_ + cs * 8);
            }
        }
        {
            const half* vgB = vbase + (size_t)(j * BC + 32) * D_;
            for (int s = tid; s < 2048; s += NTHREAD) {
                int r = s >> 6, cs = s & 63;
                cp16(smem_u32(&VBb[r * PITCH + cs * 8]), vgB + (size_t)r * D_ + cs * 8);
            }
        }
        CP_COMMIT();   // g1
        __syncthreads();   // A: partial maxes visible

        float4 pm0 = *(float4*)&sMax[r0 * 4];
        float4 pm1 = *(float4*)&sMax[r1 * 4];
        float mnew0 = fmaxf(fmaxf(fmaxf(pm0.x, pm0.y), fmaxf(pm0.z, pm0.w)), mrow0);
        float mnew1 = fmaxf(fmaxf(fmaxf(pm1.x, pm1.y), fmaxf(pm1.z, pm1.w)), mrow1);

        float p[2][4];
        #pragma unroll
        for (int nt = 0; nt < 2; nt++) {
            p[nt][0] = __expf(accS[nt][0] - mnew0);
            p[nt][1] = __expf(accS[nt][1] - mnew0);
            p[nt][2] = __expf(accS[nt][2] - mnew1);
            p[nt][3] = __expf(accS[nt][3] - mnew1);
        }
        float s0 = p[0][0] + p[0][1] + p[1][0] + p[1][1];
        float s1 = p[0][2] + p[0][3] + p[1][2] + p[1][3];
        s0 += __shfl_xor_sync(0xffffffffu, s0, 1);
        s0 += __shfl_xor_sync(0xffffffffu, s0, 2);
        s1 += __shfl_xor_sync(0xffffffffu, s1, 1);
        s1 += __shfl_xor_sync(0xffffffffu, s1, 2);

        float alpha0 = __expf(mrow0 - mnew0);
        float alpha1 = __expf(mrow1 - mnew1);
        mrow0 = mnew0; mrow1 = mnew1;

        if ((lane & 3) == 0) {
            sSum[r0 * 4 + cg] = s0;
            sSum[r1 * 4 + cg] = s1;
            if (cg == 0) { sA[r0] = alpha0; sA[r1] = alpha1; }
        }
        #pragma unroll
        for (int nt = 0; nt < 2; nt++) {
            int cl = 16 * cg + 8 * nt + (lane & 3) * 2;
            *(half2*)&Ps[r0 * PPITCH + cl] = __floats2half2_rn(p[nt][0], p[nt][1]);
            *(half2*)&Ps[r1 * PPITCH + cl] = __floats2half2_rn(p[nt][2], p[nt][3]);
        }
        // reset accS for S(j+1)
        #pragma unroll
        for (int nt = 0; nt < 2; nt++)
            #pragma unroll
            for (int i = 0; i < 4; i++) accS[nt][i] = 0.0f;

        CP_WAIT1();        // drain g2' = [VA(j), K(j+1)c0]
        __syncthreads();   // B: P, sA, sums, VA, Kc0 visible

        if (lane < 4) {
            int r = w * 4 + lane;
            float4 ss = *(float4*)&sSum[r * 4];
            sL[r] = sL[r] * sA[r] + (ss.x + ss.y + ss.z + ss.w);
        }

        // ---- rescale O ----
        #pragma unroll
        for (int mt = 0; mt < 4; mt++) {
            float a0s = sA[mt * 16 + (lane >> 2)];
            float a1s = sA[mt * 16 + 8 + (lane >> 2)];
            #pragma unroll
            for (int nt = 0; nt < 4; nt++) {
                accO[mt][nt][0] *= a0s; accO[mt][nt][1] *= a0s;
                accO[mt][nt][2] *= a1s; accO[mt][nt][3] *= a1s;
            }
        }

        // ---- merged halves: PV(j) interleaved with S(j+1) ----
        #pragma unroll
        for (int h = 0; h < 2; h++) {
            const half* vb = (h == 0) ? VAb : VBb;
            const half* kb = Kc + h * BC * KPITCH;
            #pragma unroll
            for (int i = 0; i < 16; i++) {
                if ((i & 7) == 0) {
                    const int t = i >> 3;          // PV k-step within half
                    const int k0 = t * 16;
                    uint32_t bb[4][2];
                    #pragma unroll
                    for (int h2 = 0; h2 < 2; h2++) {
                        int vr = k0 + ((lane >> 3) & 1) * 8 + (lane & 7);
                        int vc = w * 32 + h2 * 16 + (lane >> 4) * 8;
                        uint32_t t0, t1, t2, t3;
                        ldmatrix_x4_trans(t0, t1, t2, t3, smem_u32(&vb[vr * PITCH + vc]));
                        bb[2 * h2][0] = t0;     bb[2 * h2][1] = t1;
                        bb[2 * h2 + 1][0] = t2; bb[2 * h2 + 1][1] = t3;
                    }
                    #pragma unroll
                    for (int mt = 0; mt < 4; mt++) {
                        int r = mt * 16 + (lane & 7) + ((lane >> 3) & 1) * 8;
                        int c = h * 32 + k0 + (lane >> 4) * 8;
                        uint32_t a0, a1, a2, a3;
                        ldmatrix_x4(a0, a1, a2, a3, smem_u32(&Ps[r * PPITCH + c]));
                        #pragma unroll
                        for (int nt = 0; nt < 4; nt++)
                            mma16816(accO[mt][nt], a0, a1, a2, a3, bb[nt][0], bb[nt][1]);
                    }
                }
                if (more) {
                    int br = 16 * cg + ((lane >> 3) & 1) * 8 + (lane & 7);
                    int bc = i * 16 + (lane >> 4) * 8;
                    uint32_t b0, b1, b2, b3;
                    ldmatrix_x4(b0, b1, b2, b3, smem_u32(&kb[br * KPITCH + bc]));
                    int ar = 16 * rg + (lane & 7) + ((lane >> 3) & 1) * 8;
                    int ac = h * KCH + i * 16 + (lane >> 4) * 8;
                    uint32_t a0, a1, a2, a3;
                    ldmatrix_x4(a0, a1, a2, a3, smem_u32(&Qs[ar * PITCH + ac]));
                    mma16816(accS[0], a0, a1, a2, a3, b0, b2);
                    mma16816(accS[1], a0, a1, a2, a3, b1, b3);
                }
            }

            if (h == 0) {
                __syncthreads();   // C: VA + Kc0 reads done
                // g2 = [VA(j+1), K(j+2)c0]
                if (more) {
                    const half* vgA = vbase + (size_t)((j + 1) * BC) * D_;
                    for (int s = tid; s < 2048; s += NTHREAD) {
                        int r = s >> 6, cs = s & 63;
                        cp16(smem_u32(&VAb[r * PITCH + cs * 8]), vgA + (size_t)r * D_ + cs * 8);
                    }
                }
                if (j + 1 < qt) {
                    const half* kg0 = kbase + (size_t)((j + 2) * BC) * D_;
                    for (int s = tid; s < 2048; s += NTHREAD) {
                        int r = s >> 5, cs = s & 31;
                        cp16(smem_u32(&Kc[r * KPITCH + cs * 8]), kg0 + (size_t)r * D_ + cs * 8);
                    }
                }
                CP_COMMIT();       // g2
                CP_WAIT1();        // drain g1 = [K(j+1)c1, VB(j)]
                __syncthreads();   // C2: Kc1 + VB visible
            }
        }
        __syncthreads();           // D: half1 reads done before next iter's writes
    }

    // ---- epilogue: O / l -> global ----
    float* obase = Og + (size_t)(b * S_ + qt * BR) * D_;
    #pragma unroll
    for (int mt = 0; mt < 4; mt++) {
        int er0 = mt * 16 + (lane >> 2);
        float il0 = 1.0f / sL[er0];
        float il1 = 1.0f / sL[er0 + 8];
        #pragma unroll
        for (int nt = 0; nt < 4; nt++) {
            int c = w * 32 + nt * 8 + (lane & 3) * 2;
            *(float2*)(obase + (size_t)er0 * D_ + c) =
                make_float2(accO[mt][nt][0] * il0, accO[mt][nt][1] * il0);
            *(float2*)(obase + (size_t)(er0 + 8) * D_ + c) =
                make_float2(accO[mt][nt][2] * il1, accO[mt][nt][3] * il1);
        }
    }
}

extern "C" void kernel_launch(void* const* d_in, const int* in_sizes, int n_in,
                              void* d_out, int out_size) {
    const float* Q = (const float*)d_in[0];
    const float* K = (const float*)d_in[1];
    const float* V = (const float*)d_in[2];
    float* O = (float*)d_out;

    // fp32 -> fp16 pre-pass (one-time per launch)
    const int nblk = (B_ * S_ * D_) / (256 * 4);   // 16384
    cvt_kernel<<<nblk, 256>>>(Q, 0);
    cvt_kernel<<<nblk, 256>>>(K, 1);
    cvt_kernel<<<nblk, 256>>>(V, 2);

    const int smem_bytes = (BR * PITCH) * 2            // Q       66560
                         + (2 * BC * KPITCH) * 2       // K slots 67584
                         + (2 * 32 * PITCH) * 2        // VA+VB   66560
                         + BR * PPITCH * 2             // P        9216
                         + BR * 4 * 4                  // sMax     1024
                         + BR * 4 * 4                  // sSum     1024
                         + BR * 4                      // sA        256
                         + BR * 4;                     // sL        256
    cudaFuncSetAttribute(attn_fa_kernel, cudaFuncAttributeMaxDynamicSharedMemorySize, smem_bytes);

    dim3 grid(S_ / BR, B_);
    attn_fa_kernel<<<grid, NTHREAD, smem_bytes>>>(O);
}